// round 1
// baseline (speedup 1.0000x reference)
#include <cuda_runtime.h>
#include <stdint.h>

#define NN 4096
#define FC 256      // F_IN == F_OUT
#define BB 8
#define WORDS (NN / 32)   // 128 bitmask words per row

// ---------------- scratch (no allocations allowed) ----------------
__device__ uint32_t g_adj[NN * WORDS];          // 2 MB bitmask adjacency
__device__ float    g_inv_deg[NN];              // 16 KB
__device__ float    g_xt[(size_t)BB * NN * FC]; // 32 MB: xt = x @ W

// ---------------- kernel 1: clear adjacency ----------------
__global__ void k_clear_adj() {
    int i = blockIdx.x * blockDim.x + threadIdx.x;
    if (i < NN * WORDS) g_adj[i] = 0u;
}

// ---------------- kernel 2: scatter edges (atomicOr dedupes) ----------------
__global__ void k_scatter(const int* __restrict__ ei, int E) {
    int e = blockIdx.x * blockDim.x + threadIdx.x;
    if (e < E) {
        int src = ei[e];        // edge_index[0][e]
        int dst = ei[E + e];    // edge_index[1][e]
        atomicOr(&g_adj[src * WORDS + (dst >> 5)], 1u << (dst & 31));
    }
}

// ---------------- kernel 3: degree -> reciprocal ----------------
__global__ void k_degree() {
    int i = blockIdx.x * blockDim.x + threadIdx.x;
    if (i < NN) {
        int c = 0;
#pragma unroll 16
        for (int w = 0; w < WORDS; w++) c += __popc(g_adj[i * WORDS + w]);
        g_inv_deg[i] = 1.0f / ((float)c + 1e-6f);
    }
}

// ---------------- kernel 4: xt = x @ W   (fp32 SGEMM 128x128x8) ----------------
// A: [M, FC] row-major (M = BB*NN = 32768), W: [FC, FC], C -> g_xt
#define BM 128
#define BN 128
#define BK 8
__global__ __launch_bounds__(256, 2) void k_gemm(const float* __restrict__ A,
                                                 const float* __restrict__ W) {
    __shared__ float As[BK][BM];
    __shared__ float Bs[BK][BN];

    const int bm = blockIdx.x * BM;
    const int bn = blockIdx.y * BN;
    const int tid = threadIdx.x;

    const int tr = tid >> 4;    // 0..15 : row group (8 rows)
    const int tc = tid & 15;    // 0..15 : col group (8 cols)

    // global-load mapping
    const int a_row = tid >> 1;         // 0..127
    const int a_col = (tid & 1) * 4;    // 0 or 4
    const int b_row = tid >> 5;         // 0..7
    const int b_col = (tid & 31) * 4;   // 0..124

    float acc[8][8];
#pragma unroll
    for (int i = 0; i < 8; i++)
#pragma unroll
        for (int j = 0; j < 8; j++) acc[i][j] = 0.0f;

    for (int k0 = 0; k0 < FC; k0 += BK) {
        float4 av = *(const float4*)&A[(size_t)(bm + a_row) * FC + k0 + a_col];
        As[a_col + 0][a_row] = av.x;
        As[a_col + 1][a_row] = av.y;
        As[a_col + 2][a_row] = av.z;
        As[a_col + 3][a_row] = av.w;
        *(float4*)&Bs[b_row][b_col] =
            *(const float4*)&W[(size_t)(k0 + b_row) * FC + bn + b_col];
        __syncthreads();

#pragma unroll
        for (int k = 0; k < BK; k++) {
            float af[8], bf[8];
            *(float4*)&af[0] = *(const float4*)&As[k][tr * 8];
            *(float4*)&af[4] = *(const float4*)&As[k][tr * 8 + 4];
            *(float4*)&bf[0] = *(const float4*)&Bs[k][tc * 8];
            *(float4*)&bf[4] = *(const float4*)&Bs[k][tc * 8 + 4];
#pragma unroll
            for (int i = 0; i < 8; i++)
#pragma unroll
                for (int j = 0; j < 8; j++) acc[i][j] += af[i] * bf[j];
        }
        __syncthreads();
    }

#pragma unroll
    for (int i = 0; i < 8; i++) {
        const size_t r = (size_t)(bm + tr * 8 + i) * FC + bn + tc * 8;
        *(float4*)&g_xt[r]     = make_float4(acc[i][0], acc[i][1], acc[i][2], acc[i][3]);
        *(float4*)&g_xt[r + 4] = make_float4(acc[i][4], acc[i][5], acc[i][6], acc[i][7]);
    }
}

// ---------------- kernel 5: out[b,i,:] = inv_deg[i] * sum_nbr xt[b,j,:] + bias ----------------
__global__ __launch_bounds__(256) void k_aggregate(const float* __restrict__ bias,
                                                   float* __restrict__ out) {
    __shared__ int   s_nbr[NN];   // worst-case full row
    __shared__ int   s_cnt;

    const int i = blockIdx.x;   // node (row of adj)
    const int b = blockIdx.y;   // batch
    const int f = threadIdx.x;  // feature

    if (f == 0) s_cnt = 0;
    __syncthreads();

    // expand bitmask row into neighbor list
    for (int w = threadIdx.x; w < WORDS; w += blockDim.x) {
        uint32_t m = g_adj[i * WORDS + w];
        while (m) {
            int bit = __ffs(m) - 1;
            m &= m - 1;
            int pos = atomicAdd(&s_cnt, 1);
            s_nbr[pos] = w * 32 + bit;
        }
    }
    __syncthreads();

    const int n = s_cnt;
    const float* __restrict__ xb = g_xt + (size_t)b * NN * FC;

    float a0 = 0.f, a1 = 0.f, a2 = 0.f, a3 = 0.f;
    int k = 0;
    for (; k + 4 <= n; k += 4) {
        int j0 = s_nbr[k], j1 = s_nbr[k + 1], j2 = s_nbr[k + 2], j3 = s_nbr[k + 3];
        a0 += xb[(size_t)j0 * FC + f];
        a1 += xb[(size_t)j1 * FC + f];
        a2 += xb[(size_t)j2 * FC + f];
        a3 += xb[(size_t)j3 * FC + f];
    }
    for (; k < n; k++) a0 += xb[(size_t)s_nbr[k] * FC + f];

    float r = (a0 + a1 + a2 + a3) * g_inv_deg[i] + bias[f];
    out[((size_t)b * NN + i) * FC + f] = r;
}

// ---------------- launch ----------------
extern "C" void kernel_launch(void* const* d_in, const int* in_sizes, int n_in,
                              void* d_out, int out_size) {
    const float* x    = (const float*)d_in[0];  // (B, N, F_IN)
    const int*   ei   = (const int*)d_in[1];    // (2, E)
    const float* w    = (const float*)d_in[2];  // (F_IN, F_OUT)
    const float* bias = (const float*)d_in[3];  // (F_OUT,)
    float*       out  = (float*)d_out;          // (B, N, F_OUT)

    const int E = in_sizes[1] / 2;
    const int M = BB * NN;

    k_clear_adj<<<(NN * WORDS + 255) / 256, 256>>>();
    k_scatter<<<(E + 255) / 256, 256>>>(ei, E);
    k_degree<<<(NN + 255) / 256, 256>>>();

    dim3 ggrid(M / BM, FC / BN);
    k_gemm<<<ggrid, 256>>>(x, w);

    dim3 agrid(NN, BB);
    k_aggregate<<<agrid, 256>>>(bias, out);
}

// round 2
// speedup vs baseline: 2.0388x; 2.0388x over previous
#include <cuda_runtime.h>
#include <cuda_fp16.h>
#include <stdint.h>

#define NN 4096
#define FC 256      // F_IN == F_OUT
#define BB 8
#define WORDS (NN / 32)   // 128 bitmask words per row

// ---------------- scratch (no allocations allowed) ----------------
__device__ uint32_t g_adj[NN * WORDS];           // 2 MB bitmask adjacency
__device__ float    g_inv_deg[NN];               // 16 KB
__device__ __half   g_xt[(size_t)BB * NN * FC];  // 16 MB: xt = x @ W (fp16)

// ---------------- kernel 1: clear adjacency ----------------
__global__ void k_clear_adj() {
    int i = blockIdx.x * blockDim.x + threadIdx.x;
    if (i < NN * WORDS) g_adj[i] = 0u;
}

// ---------------- kernel 2: scatter edges (atomicOr dedupes) ----------------
__global__ void k_scatter(const int* __restrict__ ei, int E) {
    int e = blockIdx.x * blockDim.x + threadIdx.x;
    if (e < E) {
        int src = ei[e];        // edge_index[0][e]
        int dst = ei[E + e];    // edge_index[1][e]
        atomicOr(&g_adj[src * WORDS + (dst >> 5)], 1u << (dst & 31));
    }
}

// ---------------- kernel 3: degree -> reciprocal ----------------
__global__ void k_degree() {
    int i = blockIdx.x * blockDim.x + threadIdx.x;
    if (i < NN) {
        int c = 0;
#pragma unroll 16
        for (int w = 0; w < WORDS; w++) c += __popc(g_adj[i * WORDS + w]);
        g_inv_deg[i] = 1.0f / ((float)c + 1e-6f);
    }
}

// ---------------- tf32 helpers ----------------
__device__ __forceinline__ uint32_t f2tf32(float f) {
    uint32_t u;
    asm("cvt.rna.tf32.f32 %0, %1;" : "=r"(u) : "f"(f));
    return u;
}

__device__ __forceinline__ void mma_tf32(float* d, const uint32_t* a, const uint32_t* b) {
    asm volatile(
        "mma.sync.aligned.m16n8k8.row.col.f32.tf32.tf32.f32 "
        "{%0,%1,%2,%3}, {%4,%5,%6,%7}, {%8,%9}, {%0,%1,%2,%3};"
        : "+f"(d[0]), "+f"(d[1]), "+f"(d[2]), "+f"(d[3])
        : "r"(a[0]), "r"(a[1]), "r"(a[2]), "r"(a[3]),
          "r"(b[0]), "r"(b[1]));
}

// ---------------- kernel 4: xt = x @ W  (tf32 tensor-core GEMM) ----------------
// A: [M, FC] row-major (M = BB*NN = 32768), W: [FC, FC], output g_xt (fp16)
// Block tile 128x128, BK=32, 8 warps as 2(m)x4(n) -> warp tile 64x32.
#define BM 128
#define BN 128
#define BK 32
#define AS_ST 36   // padded stride: frag LDS conflict-free
#define BS_ST 35   // padded stride: transpose STS conflict-free, frag LDS ~2-way

__global__ __launch_bounds__(256, 2) void k_gemm(const float* __restrict__ A,
                                                 const float* __restrict__ W) {
    __shared__ uint32_t As[BM * AS_ST];   // 18 KB  (A tile, tf32 bits, [m][k])
    __shared__ uint32_t Bs[BN * BS_ST];   // 17.5 KB (B tile transposed, [n][k])

    const int tid  = threadIdx.x;
    const int lane = tid & 31;
    const int wid  = tid >> 5;
    const int wm = (wid & 1) * 64;   // warp m-offset within block
    const int wn = (wid >> 1) * 32;  // warp n-offset within block
    const int bm = blockIdx.x * BM;
    const int bn = blockIdx.y * BN;

    const int g  = lane >> 2;  // groupID (0..7)
    const int tg = lane & 3;   // thread-in-group (0..3)

    float acc[4][4][4];
#pragma unroll
    for (int mt = 0; mt < 4; mt++)
#pragma unroll
        for (int nt = 0; nt < 4; nt++)
#pragma unroll
            for (int r = 0; r < 4; r++) acc[mt][nt][r] = 0.0f;

    for (int k0 = 0; k0 < FC; k0 += BK) {
        // --- load A tile 128x32 (float4, row-major) ---
#pragma unroll
        for (int p = 0; p < 4; p++) {
            int m  = p * 32 + (tid >> 3);
            int kc = (tid & 7) * 4;
            float4 v = *(const float4*)&A[(size_t)(bm + m) * FC + k0 + kc];
            uint4 u;
            u.x = f2tf32(v.x); u.y = f2tf32(v.y);
            u.z = f2tf32(v.z); u.w = f2tf32(v.w);
            *(uint4*)&As[m * AS_ST + kc] = u;
        }
        // --- load B tile 32x128, store transposed [n][k] (scalar, coalesced LDG,
        //     conflict-free STS thanks to stride 35) ---
#pragma unroll
        for (int p = 0; p < 16; p++) {
            int k = p * 2 + (tid >> 7);
            int n = tid & 127;
            float v = W[(size_t)(k0 + k) * FC + bn + n];
            Bs[n * BS_ST + k] = f2tf32(v);
        }
        __syncthreads();

#pragma unroll
        for (int s = 0; s < 4; s++) {   // 4 k8-steps per BK=32
            uint32_t a[4][4], b[4][2];
            const int kk = s * 8 + tg;
#pragma unroll
            for (int mt = 0; mt < 4; mt++) {
                int r = wm + mt * 16 + g;
                a[mt][0] = As[r * AS_ST + kk];
                a[mt][1] = As[(r + 8) * AS_ST + kk];
                a[mt][2] = As[r * AS_ST + kk + 4];
                a[mt][3] = As[(r + 8) * AS_ST + kk + 4];
            }
#pragma unroll
            for (int nt = 0; nt < 4; nt++) {
                int c = wn + nt * 8 + g;
                b[nt][0] = Bs[c * BS_ST + kk];
                b[nt][1] = Bs[c * BS_ST + kk + 4];
            }
#pragma unroll
            for (int mt = 0; mt < 4; mt++)
#pragma unroll
                for (int nt = 0; nt < 4; nt++)
                    mma_tf32(acc[mt][nt], a[mt], b[nt]);
        }
        __syncthreads();
    }

    // --- epilogue: fp32 acc -> fp16 g_xt ---
#pragma unroll
    for (int mt = 0; mt < 4; mt++) {
#pragma unroll
        for (int nt = 0; nt < 4; nt++) {
            int r = bm + wm + mt * 16 + g;
            int c = bn + wn + nt * 8 + tg * 2;
            __half2 h01 = __floats2half2_rn(acc[mt][nt][0], acc[mt][nt][1]);
            __half2 h23 = __floats2half2_rn(acc[mt][nt][2], acc[mt][nt][3]);
            *(__half2*)&g_xt[(size_t)r * FC + c]       = h01;
            *(__half2*)&g_xt[(size_t)(r + 8) * FC + c] = h23;
        }
    }
}

// ---------------- kernel 5: aggregate, all 8 batches per block ----------------
// out[b,i,:] = inv_deg[i] * sum_{j in N(i)} xt[b,j,:] + bias
__global__ __launch_bounds__(128) void k_aggregate(const float* __restrict__ bias,
                                                   float* __restrict__ out) {
    __shared__ int s_nbr[NN];
    __shared__ int s_cnt;

    const int i = blockIdx.x;     // node (row of adj)
    const int t = threadIdx.x;    // feature-pair index (0..127)
    const int f2 = t * 2;

    if (t == 0) s_cnt = 0;
    __syncthreads();

    // expand bitmask row into neighbor list
    {
        uint32_t m = g_adj[i * WORDS + t];
        while (m) {
            int bit = __ffs(m) - 1;
            m &= m - 1;
            int pos = atomicAdd(&s_cnt, 1);
            s_nbr[pos] = t * 32 + bit;
        }
    }
    __syncthreads();

    const int n = s_cnt;
    float2 acc[BB];
#pragma unroll
    for (int b = 0; b < BB; b++) acc[b] = make_float2(0.f, 0.f);

    for (int k = 0; k < n; k++) {
        const int j = s_nbr[k];
#pragma unroll
        for (int b = 0; b < BB; b++) {
            __half2 h = *(const __half2*)&g_xt[((size_t)b * NN + j) * FC + f2];
            float2 v = __half22float2(h);
            acc[b].x += v.x;
            acc[b].y += v.y;
        }
    }

    const float inv = g_inv_deg[i];
    const float bx = bias[f2], by = bias[f2 + 1];
#pragma unroll
    for (int b = 0; b < BB; b++) {
        float2 r;
        r.x = acc[b].x * inv + bx;
        r.y = acc[b].y * inv + by;
        *(float2*)&out[((size_t)b * NN + i) * FC + f2] = r;
    }
}

// ---------------- launch ----------------
extern "C" void kernel_launch(void* const* d_in, const int* in_sizes, int n_in,
                              void* d_out, int out_size) {
    const float* x    = (const float*)d_in[0];  // (B, N, F_IN)
    const int*   ei   = (const int*)d_in[1];    // (2, E)
    const float* w    = (const float*)d_in[2];  // (F_IN, F_OUT)
    const float* bias = (const float*)d_in[3];  // (F_OUT,)
    float*       out  = (float*)d_out;          // (B, N, F_OUT)

    const int E = in_sizes[1] / 2;
    const int M = BB * NN;

    k_clear_adj<<<(NN * WORDS + 255) / 256, 256>>>();
    k_scatter<<<(E + 255) / 256, 256>>>(ei, E);
    k_degree<<<(NN + 255) / 256, 256>>>();

    dim3 ggrid(M / BM, FC / BN);
    k_gemm<<<ggrid, 256>>>(x, w);

    k_aggregate<<<NN, 128>>>(bias, out);
}

// round 4
// speedup vs baseline: 2.7669x; 1.3571x over previous
#include <cuda_runtime.h>
#include <cuda_fp16.h>
#include <stdint.h>

#define NN 4096
#define FC 256      // F_IN == F_OUT
#define BB 8
#define WORDS (NN / 32)

// ---------------- scratch (no allocations allowed) ----------------
__device__ uint32_t g_adj[NN * WORDS];            // 2 MB bitmask adjacency
__device__ float    g_inv_deg[NN];                // 16 KB
__device__ __half   g_xt[(size_t)BB * NN * FC];   // 16 MB: xt = x @ W (fp16)
__device__ float    g_wtf[FC * FC];               // 256 KB: W^T (float) [n][k]

// =================== setup kernels ===================
__global__ void k_clear_adj() {
    int i = blockIdx.x * blockDim.x + threadIdx.x;
    if (i < NN * WORDS) g_adj[i] = 0u;
}
__global__ void k_scatter(const int* __restrict__ ei, int E) {
    int e = blockIdx.x * blockDim.x + threadIdx.x;
    if (e < E) {
        int src = ei[e];
        int dst = ei[E + e];
        atomicOr(&g_adj[src * WORDS + (dst >> 5)], 1u << (dst & 31));
    }
}
__global__ void k_degree() {
    int i = blockIdx.x * blockDim.x + threadIdx.x;
    if (i < NN) {
        int c = 0;
#pragma unroll 16
        for (int w = 0; w < WORDS; w++) c += __popc(g_adj[i * WORDS + w]);
        g_inv_deg[i] = 1.0f / ((float)c + 1e-6f);
    }
}
// W[k][n] -> g_wtf[n][k] (plain float transpose)
__global__ void k_wt(const float* __restrict__ W) {
    int i = blockIdx.x * blockDim.x + threadIdx.x;
    if (i < FC * FC) {
        int k = i >> 8, n = i & 255;
        g_wtf[n * FC + k] = W[i];
    }
}

// =================== mma / cp.async helpers ===================
__device__ __forceinline__ void mma_tf32(float* d, const uint32_t* a, const uint32_t* b) {
    asm volatile(
        "mma.sync.aligned.m16n8k8.row.col.f32.tf32.tf32.f32 "
        "{%0,%1,%2,%3}, {%4,%5,%6,%7}, {%8,%9}, {%0,%1,%2,%3};"
        : "+f"(d[0]), "+f"(d[1]), "+f"(d[2]), "+f"(d[3])
        : "r"(a[0]), "r"(a[1]), "r"(a[2]), "r"(a[3]),
          "r"(b[0]), "r"(b[1]));
}
__device__ __forceinline__ uint32_t smem_u32(const void* p) {
    uint32_t a;
    asm("{ .reg .u64 t; cvta.to.shared.u64 t, %1; cvt.u32.u64 %0, t; }" : "=r"(a) : "l"(p));
    return a;
}
#define CP_ASYNC16(dst, src) \
    asm volatile("cp.async.cg.shared.global [%0], [%1], 16;" :: "r"(dst), "l"(src))
#define CP_COMMIT() asm volatile("cp.async.commit_group;" ::: "memory")
#define CP_WAIT0()  asm volatile("cp.async.wait_group 0;" ::: "memory")
#define CP_WAIT1()  asm volatile("cp.async.wait_group 1;" ::: "memory")

// XOR-swizzled word index inside one 128x32 tile: row*32 + (k ^ ((row&7)<<2)).
// Aligned groups of 4 words map to aligned groups of 4 -> cp.async.16 safe,
// fragment LDS conflict-free.
#define SWX(row, k) ((row) * 32 + ((k) ^ (((row) & 7) << 2)))

// =================== kernel: xt = x @ W  (tf32 mma.sync, cp.async pipeline) ===================
// Block tile 128x128, BK=32, 8 warps as 2(m)x4(n) -> warp tile 64x32.
#define BM 128
#define BN 128
#define BK 32
#define TILE_W  (128 * 32)            // words per 128x32 tile
#define A_OFF(p) ((p) * TILE_W)
#define B_OFF(p) (2 * TILE_W + (p) * TILE_W)
#define GEMM_SMEM (4 * TILE_W * 4)    // 64 KB

__global__ __launch_bounds__(256, 2) void k_gemm(const float* __restrict__ A) {
    extern __shared__ uint32_t sm[];
    const uint32_t sb = smem_u32(sm);

    const int tid  = threadIdx.x;
    const int lane = tid & 31;
    const int wid  = tid >> 5;
    const int wm = (wid & 1) * 64;
    const int wn = (wid >> 1) * 32;
    const int bm = blockIdx.x * BM;
    const int bn = blockIdx.y * BN;
    const int g  = lane >> 2;
    const int tg = lane & 3;

    // cp.async source mapping: id = q*256 + tid -> row = id>>3, 16B chunk t4 = id&7
    const int cp_row = tid >> 3;        // base row when q contributes +32*q
    const int cp_t4  = (tid & 7) * 4;   // word offset of the 16B chunk

    float acc[4][4][4];
#pragma unroll
    for (int mt = 0; mt < 4; mt++)
#pragma unroll
        for (int nt = 0; nt < 4; nt++)
#pragma unroll
            for (int r = 0; r < 4; r++) acc[mt][nt][r] = 0.0f;

    // ---- issue one chunk's loads into buffer p ----
    auto issue = [&](int c, int p) {
        const int k0 = c * BK;
#pragma unroll
        for (int q = 0; q < 4; q++) {
            int m = q * 32 + cp_row;
            uint32_t dst = sb + (A_OFF(p) + SWX(m, cp_t4)) * 4;
            CP_ASYNC16(dst, &A[(size_t)(bm + m) * FC + k0 + cp_t4]);
        }
#pragma unroll
        for (int q = 0; q < 4; q++) {
            int n = q * 32 + cp_row;
            uint32_t dst = sb + (B_OFF(p) + SWX(n, cp_t4)) * 4;
            CP_ASYNC16(dst, &g_wtf[(size_t)(bn + n) * FC + k0 + cp_t4]);
        }
        CP_COMMIT();
    };

    issue(0, 0);
    issue(1, 1);

#pragma unroll
    for (int c = 0; c < FC / BK; c++) {
        const int p = c & 1;
        if (c == FC / BK - 1) { CP_WAIT0(); } else { CP_WAIT1(); }
        __syncthreads();

        const uint32_t* As = sm + A_OFF(p);
        const uint32_t* Bs = sm + B_OFF(p);
#pragma unroll
        for (int s = 0; s < 4; s++) {
            const int kk = s * 8 + tg;
            uint32_t a[4][4], b[4][2];
#pragma unroll
            for (int mt = 0; mt < 4; mt++) {
                int r = wm + mt * 16 + g;
                a[mt][0] = As[SWX(r, kk)];
                a[mt][1] = As[SWX(r + 8, kk)];
                a[mt][2] = As[SWX(r, kk + 4)];
                a[mt][3] = As[SWX(r + 8, kk + 4)];
            }
#pragma unroll
            for (int nt = 0; nt < 4; nt++) {
                int cc = wn + nt * 8 + g;
                b[nt][0] = Bs[SWX(cc, kk)];
                b[nt][1] = Bs[SWX(cc, kk + 4)];
            }
#pragma unroll
            for (int mt = 0; mt < 4; mt++)
#pragma unroll
                for (int nt = 0; nt < 4; nt++)
                    mma_tf32(acc[mt][nt], a[mt], b[nt]);
        }
        __syncthreads();
        if (c + 2 < FC / BK) issue(c + 2, p);
    }

    // ---- epilogue: fp32 acc -> fp16 g_xt ----
#pragma unroll
    for (int mt = 0; mt < 4; mt++) {
#pragma unroll
        for (int nt = 0; nt < 4; nt++) {
            int r = bm + wm + mt * 16 + g;
            int c = bn + wn + nt * 8 + tg * 2;
            __half2 h01 = __floats2half2_rn(acc[mt][nt][0], acc[mt][nt][1]);
            __half2 h23 = __floats2half2_rn(acc[mt][nt][2], acc[mt][nt][3]);
            *(__half2*)&g_xt[(size_t)r * FC + c]       = h01;
            *(__half2*)&g_xt[(size_t)(r + 8) * FC + c] = h23;
        }
    }
}

// =================== kernel: aggregate (wide loads, 8 warps) ===================
// thread t: batch b = t>>5, features f8 = (t&31)*8 .. +7 (one LDG.128 / neighbor)
__global__ __launch_bounds__(256) void k_aggregate(const float* __restrict__ bias,
                                                   float* __restrict__ out) {
    __shared__ int s_nbr[NN];
    __shared__ int s_cnt;

    const int i = blockIdx.x;
    const int t = threadIdx.x;
    const int b  = t >> 5;
    const int f8 = (t & 31) * 8;

    if (t == 0) s_cnt = 0;
    __syncthreads();

    if (t < WORDS) {
        uint32_t m = g_adj[i * WORDS + t];
        while (m) {
            int bit = __ffs(m) - 1;
            m &= m - 1;
            int pos = atomicAdd(&s_cnt, 1);
            s_nbr[pos] = t * 32 + bit;
        }
    }
    __syncthreads();

    const int n = s_cnt;
    const __half* __restrict__ xb = g_xt + (size_t)b * NN * FC + f8;

    float a0 = 0.f, a1 = 0.f, a2 = 0.f, a3 = 0.f;
    float a4 = 0.f, a5 = 0.f, a6 = 0.f, a7 = 0.f;

    int k = 0;
    for (; k + 2 <= n; k += 2) {
        const int j0 = s_nbr[k], j1 = s_nbr[k + 1];
        uint4 v0 = *(const uint4*)&xb[(size_t)j0 * FC];
        uint4 v1 = *(const uint4*)&xb[(size_t)j1 * FC];
        const __half2* h0 = (const __half2*)&v0;
        const __half2* h1 = (const __half2*)&v1;
        float2 p;
        p = __half22float2(h0[0]); a0 += p.x; a1 += p.y;
        p = __half22float2(h0[1]); a2 += p.x; a3 += p.y;
        p = __half22float2(h0[2]); a4 += p.x; a5 += p.y;
        p = __half22float2(h0[3]); a6 += p.x; a7 += p.y;
        p = __half22float2(h1[0]); a0 += p.x; a1 += p.y;
        p = __half22float2(h1[1]); a2 += p.x; a3 += p.y;
        p = __half22float2(h1[2]); a4 += p.x; a5 += p.y;
        p = __half22float2(h1[3]); a6 += p.x; a7 += p.y;
    }
    if (k < n) {
        uint4 v0 = *(const uint4*)&xb[(size_t)s_nbr[k] * FC];
        const __half2* h0 = (const __half2*)&v0;
        float2 p;
        p = __half22float2(h0[0]); a0 += p.x; a1 += p.y;
        p = __half22float2(h0[1]); a2 += p.x; a3 += p.y;
        p = __half22float2(h0[2]); a4 += p.x; a5 += p.y;
        p = __half22float2(h0[3]); a6 += p.x; a7 += p.y;
    }

    const float inv = g_inv_deg[i];
    float4 bl = *(const float4*)&bias[f8];
    float4 bh = *(const float4*)&bias[f8 + 4];
    float* o = out + ((size_t)b * NN + i) * FC + f8;
    *(float4*)o       = make_float4(a0 * inv + bl.x, a1 * inv + bl.y,
                                    a2 * inv + bl.z, a3 * inv + bl.w);
    *(float4*)(o + 4) = make_float4(a4 * inv + bh.x, a5 * inv + bh.y,
                                    a6 * inv + bh.z, a7 * inv + bh.w);
}

// =================== launch ===================
extern "C" void kernel_launch(void* const* d_in, const int* in_sizes, int n_in,
                              void* d_out, int out_size) {
    const float* x    = (const float*)d_in[0];
    const int*   ei   = (const int*)d_in[1];
    const float* w    = (const float*)d_in[2];
    const float* bias = (const float*)d_in[3];
    float*       out  = (float*)d_out;

    const int E = in_sizes[1] / 2;
    const int M = BB * NN;

    cudaFuncSetAttribute(k_gemm, cudaFuncAttributeMaxDynamicSharedMemorySize,
                         GEMM_SMEM);

    k_clear_adj<<<(NN * WORDS + 255) / 256, 256>>>();
    k_scatter<<<(E + 255) / 256, 256>>>(ei, E);
    k_degree<<<(NN + 255) / 256, 256>>>();
    k_wt<<<(FC * FC + 255) / 256, 256>>>(w);

    dim3 ggrid(M / BM, FC / BN);
    k_gemm<<<ggrid, 256, GEMM_SMEM>>>(x);

    k_aggregate<<<NN, 256>>>(bias, out);
}

// round 5
// speedup vs baseline: 3.3051x; 1.1945x over previous
#include <cuda_runtime.h>
#include <cuda_fp16.h>
#include <stdint.h>

#define NN 4096
#define FC 256      // F_IN == F_OUT
#define BB 8
#define WORDS (NN / 32)

// ---------------- scratch (no allocations allowed) ----------------
__device__ uint32_t g_adj[NN * WORDS];            // 2 MB bitmask adjacency
__device__ __half   g_xt[(size_t)BB * NN * FC];   // 16 MB: xt = x @ W (fp16)
__device__ uint32_t g_wt[FC * FC];                // 256 KB: W^T, tf32(RNA) bits [n][k]

// =================== setup kernels ===================
__global__ void k_clear_adj() {
    int i = blockIdx.x * blockDim.x + threadIdx.x;
    if (i < NN * WORDS) g_adj[i] = 0u;
}
__global__ void k_scatter(const int* __restrict__ ei, int E) {
    int e = blockIdx.x * blockDim.x + threadIdx.x;
    if (e < E) {
        int src = ei[e];
        int dst = ei[E + e];
        atomicOr(&g_adj[src * WORDS + (dst >> 5)], 1u << (dst & 31));
    }
}
__device__ __forceinline__ uint32_t f2tf32(float f) {
    uint32_t u;
    asm("cvt.rna.tf32.f32 %0, %1;" : "=r"(u) : "f"(f));
    return u;
}
// W[k][n] -> g_wt[n][k] as RNA-rounded tf32 bits (tiled transpose, coalesced)
__global__ void k_wt(const float* __restrict__ W) {
    __shared__ float tile[32][33];
    const int bn = blockIdx.x * 32;   // n-range of this tile
    const int bk = blockIdx.y * 32;   // k-range of this tile
    const int tx = threadIdx.x, ty = threadIdx.y;
#pragma unroll
    for (int r = ty; r < 32; r += 8)
        tile[r][tx] = W[(size_t)(bk + r) * FC + bn + tx];   // tile[k'][n']
    __syncthreads();
#pragma unroll
    for (int r = ty; r < 32; r += 8)
        g_wt[(size_t)(bn + r) * FC + bk + tx] = f2tf32(tile[tx][r]);
}

// =================== mma / cp.async helpers ===================
__device__ __forceinline__ void mma_tf32(float* d, const uint32_t* a, const uint32_t* b) {
    asm volatile(
        "mma.sync.aligned.m16n8k8.row.col.f32.tf32.tf32.f32 "
        "{%0,%1,%2,%3}, {%4,%5,%6,%7}, {%8,%9}, {%0,%1,%2,%3};"
        : "+f"(d[0]), "+f"(d[1]), "+f"(d[2]), "+f"(d[3])
        : "r"(a[0]), "r"(a[1]), "r"(a[2]), "r"(a[3]),
          "r"(b[0]), "r"(b[1]));
}
__device__ __forceinline__ uint32_t smem_u32(const void* p) {
    uint32_t a;
    asm("{ .reg .u64 t; cvta.to.shared.u64 t, %1; cvt.u32.u64 %0, t; }" : "=r"(a) : "l"(p));
    return a;
}
#define CP_ASYNC16(dst, src) \
    asm volatile("cp.async.cg.shared.global [%0], [%1], 16;" :: "r"(dst), "l"(src))
#define CP_COMMIT() asm volatile("cp.async.commit_group;" ::: "memory")
#define CP_WAIT0()  asm volatile("cp.async.wait_group 0;" ::: "memory")
#define CP_WAIT1()  asm volatile("cp.async.wait_group 1;" ::: "memory")

// XOR-swizzled word index inside one 128x32 tile.
#define SWX(row, k) ((row) * 32 + ((k) ^ (((row) & 7) << 2)))

// =================== kernel: xt = x @ W  (tf32 mma.sync, cp.async pipeline) ===================
#define BM 128
#define BN 128
#define BK 32
#define TILE_W  (128 * 32)
#define A_OFF(p) ((p) * TILE_W)
#define B_OFF(p) (2 * TILE_W + (p) * TILE_W)
#define GEMM_SMEM (4 * TILE_W * 4)    // 64 KB

__global__ __launch_bounds__(256, 2) void k_gemm(const float* __restrict__ A) {
    extern __shared__ uint32_t sm[];
    const uint32_t sb = smem_u32(sm);

    const int tid  = threadIdx.x;
    const int lane = tid & 31;
    const int wid  = tid >> 5;
    const int wm = (wid & 1) * 64;
    const int wn = (wid >> 1) * 32;
    const int bm = blockIdx.x * BM;
    const int bn = blockIdx.y * BN;
    const int g  = lane >> 2;
    const int tg = lane & 3;

    const int cp_row = tid >> 3;
    const int cp_t4  = (tid & 7) * 4;

    float acc[4][4][4];
#pragma unroll
    for (int mt = 0; mt < 4; mt++)
#pragma unroll
        for (int nt = 0; nt < 4; nt++)
#pragma unroll
            for (int r = 0; r < 4; r++) acc[mt][nt][r] = 0.0f;

    auto issue = [&](int c, int p) {
        const int k0 = c * BK;
#pragma unroll
        for (int q = 0; q < 4; q++) {
            int m = q * 32 + cp_row;
            uint32_t dst = sb + (A_OFF(p) + SWX(m, cp_t4)) * 4;
            CP_ASYNC16(dst, &A[(size_t)(bm + m) * FC + k0 + cp_t4]);
        }
#pragma unroll
        for (int q = 0; q < 4; q++) {
            int n = q * 32 + cp_row;
            uint32_t dst = sb + (B_OFF(p) + SWX(n, cp_t4)) * 4;
            CP_ASYNC16(dst, &g_wt[(size_t)(bn + n) * FC + k0 + cp_t4]);
        }
        CP_COMMIT();
    };

    issue(0, 0);
    issue(1, 1);

#pragma unroll
    for (int c = 0; c < FC / BK; c++) {
        const int p = c & 1;
        if (c == FC / BK - 1) { CP_WAIT0(); } else { CP_WAIT1(); }
        __syncthreads();

        const uint32_t* As = sm + A_OFF(p);
        const uint32_t* Bs = sm + B_OFF(p);
#pragma unroll
        for (int s = 0; s < 4; s++) {
            const int kk = s * 8 + tg;
            uint32_t a[4][4], b[4][2];
#pragma unroll
            for (int mt = 0; mt < 4; mt++) {
                int r = wm + mt * 16 + g;
                a[mt][0] = As[SWX(r, kk)];
                a[mt][1] = As[SWX(r + 8, kk)];
                a[mt][2] = As[SWX(r, kk + 4)];
                a[mt][3] = As[SWX(r + 8, kk + 4)];
            }
#pragma unroll
            for (int nt = 0; nt < 4; nt++) {
                int cc = wn + nt * 8 + g;
                b[nt][0] = Bs[SWX(cc, kk)];
                b[nt][1] = Bs[SWX(cc, kk + 4)];
            }
#pragma unroll
            for (int mt = 0; mt < 4; mt++)
#pragma unroll
                for (int nt = 0; nt < 4; nt++)
                    mma_tf32(acc[mt][nt], a[mt], b[nt]);
        }
        __syncthreads();
        if (c + 2 < FC / BK) issue(c + 2, p);
    }

#pragma unroll
    for (int mt = 0; mt < 4; mt++) {
#pragma unroll
        for (int nt = 0; nt < 4; nt++) {
            int r = bm + wm + mt * 16 + g;
            int c = bn + wn + nt * 8 + tg * 2;
            __half2 h01 = __floats2half2_rn(acc[mt][nt][0], acc[mt][nt][1]);
            __half2 h23 = __floats2half2_rn(acc[mt][nt][2], acc[mt][nt][3]);
            *(__half2*)&g_xt[(size_t)r * FC + c]       = h01;
            *(__half2*)&g_xt[(size_t)(r + 8) * FC + c] = h23;
        }
    }
}

// =================== kernel: aggregate ===================
// thread t: batch b = t>>5, features f8 = (t&31)*8 .. +7 (one LDG.128 / neighbor)
// Deterministic neighbor expansion via popc prefix scan (degree = total count).
__global__ __launch_bounds__(256) void k_aggregate(const float* __restrict__ bias,
                                                   float* __restrict__ out) {
    __shared__ int s_nbr[NN];
    __shared__ int s_off[WORDS];
    __shared__ int s_total;

    const int i = blockIdx.x;
    const int t = threadIdx.x;
    const int b  = t >> 5;
    const int f8 = (t & 31) * 8;

    uint32_t word = (t < WORDS) ? g_adj[i * WORDS + t] : 0u;
    if (t < WORDS) s_off[t] = __popc(word);
    __syncthreads();

    if (t < 32) {   // warp 0: exclusive scan of 128 popcounts, 4 per lane
        int v0 = s_off[4 * t], v1 = s_off[4 * t + 1];
        int v2 = s_off[4 * t + 2], v3 = s_off[4 * t + 3];
        int sum = v0 + v1 + v2 + v3;
        int inc = sum;
#pragma unroll
        for (int d = 1; d < 32; d <<= 1) {
            int x = __shfl_up_sync(0xFFFFFFFFu, inc, d);
            if (t >= d) inc += x;
        }
        int exc = inc - sum;
        s_off[4 * t] = exc;
        s_off[4 * t + 1] = exc + v0;
        s_off[4 * t + 2] = exc + v0 + v1;
        s_off[4 * t + 3] = exc + v0 + v1 + v2;
        if (t == 31) s_total = inc;
    }
    __syncthreads();

    if (t < WORDS) {
        int pos = s_off[t];
        uint32_t m = word;
        while (m) {
            int bit = __ffs(m) - 1;
            m &= m - 1;
            s_nbr[pos++] = t * 32 + bit;
        }
    }
    __syncthreads();

    const int n = s_total;
    const float inv = 1.0f / ((float)n + 1e-6f);
    const __half* __restrict__ xb = g_xt + (size_t)b * NN * FC + f8;

    float a0 = 0.f, a1 = 0.f, a2 = 0.f, a3 = 0.f;
    float a4 = 0.f, a5 = 0.f, a6 = 0.f, a7 = 0.f;

#define ACC8(v)                                               \
    do { const __half2* _h = (const __half2*)&(v); float2 _p; \
        _p = __half22float2(_h[0]); a0 += _p.x; a1 += _p.y;   \
        _p = __half22float2(_h[1]); a2 += _p.x; a3 += _p.y;   \
        _p = __half22float2(_h[2]); a4 += _p.x; a5 += _p.y;   \
        _p = __half22float2(_h[3]); a6 += _p.x; a7 += _p.y; } while (0)

    int k = 0;
    for (; k + 4 <= n; k += 4) {
        uint4 v0 = *(const uint4*)&xb[(size_t)s_nbr[k]     * FC];
        uint4 v1 = *(const uint4*)&xb[(size_t)s_nbr[k + 1] * FC];
        uint4 v2 = *(const uint4*)&xb[(size_t)s_nbr[k + 2] * FC];
        uint4 v3 = *(const uint4*)&xb[(size_t)s_nbr[k + 3] * FC];
        ACC8(v0); ACC8(v1); ACC8(v2); ACC8(v3);
    }
    for (; k < n; k++) {
        uint4 v0 = *(const uint4*)&xb[(size_t)s_nbr[k] * FC];
        ACC8(v0);
    }
#undef ACC8

    float4 bl = *(const float4*)&bias[f8];
    float4 bh = *(const float4*)&bias[f8 + 4];
    float* o = out + ((size_t)b * NN + i) * FC + f8;
    *(float4*)o       = make_float4(a0 * inv + bl.x, a1 * inv + bl.y,
                                    a2 * inv + bl.z, a3 * inv + bl.w);
    *(float4*)(o + 4) = make_float4(a4 * inv + bh.x, a5 * inv + bh.y,
                                    a6 * inv + bh.z, a7 * inv + bh.w);
}

// =================== launch ===================
extern "C" void kernel_launch(void* const* d_in, const int* in_sizes, int n_in,
                              void* d_out, int out_size) {
    const float* x    = (const float*)d_in[0];
    const int*   ei   = (const int*)d_in[1];
    const float* w    = (const float*)d_in[2];
    const float* bias = (const float*)d_in[3];
    float*       out  = (float*)d_out;

    const int E = in_sizes[1] / 2;
    const int M = BB * NN;

    cudaFuncSetAttribute(k_gemm, cudaFuncAttributeMaxDynamicSharedMemorySize,
                         GEMM_SMEM);

    k_clear_adj<<<(NN * WORDS + 255) / 256, 256>>>();
    k_scatter<<<(E + 255) / 256, 256>>>(ei, E);
    {
        dim3 tb(32, 8);
        dim3 tg(FC / 32, FC / 32);
        k_wt<<<tg, tb>>>(w);
    }

    dim3 ggrid(M / BM, FC / BN);
    k_gemm<<<ggrid, 256, GEMM_SMEM>>>(x);

    k_aggregate<<<NN, 256>>>(bias, out);
}